// round 13
// baseline (speedup 1.0000x reference)
#include <cuda_runtime.h>
#include <cuda_fp16.h>

#define BATCH 128
#define SEQ   256
#define UNITS 128
#define NV    512          // 4*UNITS gate width
#define DEPTH 655
#define KROWS 2620         // 4*DEPTH
#define NT    512          // threads per lstm block; thread owns ONE gate col
#define RROWS 48           // Wh rows register-resident fp32 per column
#define FROWS (UNITS - RROWS)   // 80 rows register-resident fp16 per column
#define RGRP4 (RROWS / 4)       // 12 fp32 4-row groups
#define FGRP4 (FROWS / 4)       // 20 fp16 4-row groups

// Precomputed M = W_dense @ Wx  [KROWS][NV] (natural column order),
// plus row KROWS = b_dense@Wx + b_lstm
__device__ float g_M[(KROWS + 1) * NV];

typedef unsigned long long ull;

#define FMA2(acc, a, b) \
    asm("fma.rn.f32x2 %0, %1, %2, %0;" : "+l"(acc) : "l"(a), "l"(b))

__device__ __forceinline__ ull pk(float lo, float hi) {
    return (ull)__float_as_uint(lo) | ((ull)__float_as_uint(hi) << 32);
}
__device__ __forceinline__ float red4(ull a, ull b, ull c, ull d) {
    ull s1, s2, s;
    asm("add.rn.f32x2 %0, %1, %2;" : "=l"(s1) : "l"(a), "l"(b));
    asm("add.rn.f32x2 %0, %1, %2;" : "=l"(s2) : "l"(c), "l"(d));
    asm("add.rn.f32x2 %0, %1, %2;" : "=l"(s)  : "l"(s1), "l"(s2));
    return __uint_as_float((unsigned)s) + __uint_as_float((unsigned)(s >> 32));
}
__device__ __forceinline__ float sigmoid_f(float x) {
    return __fdividef(1.f, 1.f + __expf(-x));
}
__device__ __forceinline__ float tanh_f(float x) {
    return 1.f - __fdividef(2.f, __expf(2.f * x) + 1.f);
}
// fp16 pair (packed in u32) -> packed f32x2 operand
__device__ __forceinline__ ull h2f2(unsigned u) {
    float2 f = __half22float2(*reinterpret_cast<const __half2*>(&u));
    return pk(f.x, f.y);
}
__device__ __forceinline__ unsigned f2h2(float a, float b) {
    __half2 h = __floats2half2_rn(a, b);
    return *reinterpret_cast<unsigned*>(&h);
}

// ---------------------------------------------------------------------------
__global__ void prep_bb_kernel(const float* __restrict__ b_dense,
                               const float* __restrict__ Wx,
                               const float* __restrict__ b_lstm) {
    int t = threadIdx.x;
    float acc = 0.f;
#pragma unroll 8
    for (int u = 0; u < UNITS; ++u)
        acc = fmaf(b_dense[u], Wx[u * NV + t], acc);
    g_M[KROWS * NV + t] = acc + b_lstm[t];
}

// ---------------------------------------------------------------------------
#define RPB 20
__global__ __launch_bounds__(512) void prep_M_kernel(const float* __restrict__ Wd,
                                                     const float* __restrict__ Wx) {
    __shared__ float wd[RPB * UNITS];
    const int t = threadIdx.x;
    const int r0 = blockIdx.x * RPB;
    for (int idx = t; idx < RPB * UNITS; idx += 512)
        wd[idx] = Wd[r0 * UNITS + idx];
    __syncthreads();

    float acc[RPB];
#pragma unroll
    for (int r = 0; r < RPB; ++r) acc[r] = 0.f;

    for (int u = 0; u < UNITS; u += 4) {
        float x0 = Wx[(u + 0) * NV + t];
        float x1 = Wx[(u + 1) * NV + t];
        float x2 = Wx[(u + 2) * NV + t];
        float x3 = Wx[(u + 3) * NV + t];
#pragma unroll
        for (int r = 0; r < RPB; ++r) {
            float4 w = *(const float4*)&wd[r * UNITS + u];
            acc[r] = fmaf(w.x, x0, fmaf(w.y, x1, fmaf(w.z, x2, fmaf(w.w, x3, acc[r]))));
        }
    }
#pragma unroll
    for (int r = 0; r < RPB; ++r)
        g_M[(r0 + r) * NV + t] = acc[r];
}

// ---------------------------------------------------------------------------
__global__ void ctx_kernel(const int* __restrict__ last_rule,
                           const int* __restrict__ move_count,
                           const int* __restrict__ node_count,
                           const int* __restrict__ problem_type,
                           float* __restrict__ out, int out_size) {
    const int b = blockIdx.x, j = threadIdx.x;
    if (j < 35) {
        float v;
        if (j == 0)      v = (float)last_rule[b];
        else if (j == 1) v = (float)move_count[b];
        else if (j == 2) v = (float)node_count[b];
        else             v = (problem_type[b] == (j - 3)) ? 1.f : 0.f;
        out[b * 35 + j] = v;
    }
    const int seq_off = BATCH * 35 + BATCH * UNITS + BATCH * SEQ * UNITS;
    if (b == 0 && j == 63 && out_size > seq_off)
        out[seq_off] = (float)SEQ;
}

// ---------------------------------------------------------------------------
// LSTM: one block per batch row; 512 threads (16 warps -> 4/SMSP for latency
// hiding). Warp w covers elements [8w, 8w+8). Lane l: role = l>>3 in {0..3}
// = gate {i,f,g,o}; element e = 8w + (l&7); column c = e + role*128.
// ALL Wh weights in registers per thread: rows [0,48) fp32 f32x2 pairs,
// rows [48,128) fp16-packed. Gate assembly: 3 shfl.xor (8,16,8) deliver
// f,g,o to the role-0 lane; c,h in registers; h via ping-pong smem;
// ONE __syncthreads per step.
// ---------------------------------------------------------------------------
#define SMEM_LSTM (2 * UNITS * 4 + 4 * SEQ * 4)

__global__ __launch_bounds__(NT, 1) void lstm_kernel(
    const int* __restrict__ bwd, const int* __restrict__ fwd,
    const int* __restrict__ lbwd, const int* __restrict__ lfwd,
    const float* __restrict__ Wh,
    float* __restrict__ out_h,    // [B][S][UNITS]
    float* __restrict__ out_lv) { // [B][UNITS]
    extern __shared__ unsigned char smraw[];
    float* h0  = (float*)smraw;
    float* h1  = h0 + UNITS;
    int*   idx_s = (int*)(h1 + UNITS);

    const int b = blockIdx.x;
    const int t = threadIdx.x;
    const int l = t & 31;
    const int role = l >> 3;                 // 0:i 1:f 2:g 3:o
    const int e  = (t >> 5) * 8 + (l & 7);   // element in [0,128)
    const int c  = e + role * 128;           // owned gate column

    // ---- weights: rows [0,RROWS) fp32 pairs; rows [RROWS,128) fp16 pairs ----
    ull wp[RROWS / 2];
#pragma unroll
    for (int p = 0; p < RROWS / 2; ++p)
        wp[p] = pk(Wh[(2 * p) * NV + c], Wh[(2 * p + 1) * NV + c]);
    unsigned fw[FROWS / 2];
#pragma unroll
    for (int p = 0; p < FROWS / 2; ++p) {
        int i = RROWS + 2 * p;
        fw[p] = f2h2(Wh[i * NV + c], Wh[(i + 1) * NV + c]);
    }

    // ---- stage gather indices with offsets pre-added ----
    if (t < SEQ) {
        idx_s[t]           = bwd[b * SEQ + t];
        idx_s[SEQ + t]     = DEPTH     + fwd[b * SEQ + t];
        idx_s[2 * SEQ + t] = 2 * DEPTH + lbwd[b * SEQ + t];
        idx_s[3 * SEQ + t] = 3 * DEPTH + lfwd[b * SEQ + t];
    }
    if (t < UNITS) h0[t] = 0.f;
    float c_r = 0.f, h_last = 0.f;
    const float bb = g_M[KROWS * NV + c];
    __syncthreads();

    // xz for s = 0
    float xz = g_M[idx_s[0] * NV + c] + g_M[idx_s[SEQ] * NV + c] +
               g_M[idx_s[2 * SEQ] * NV + c] + g_M[idx_s[3 * SEQ] * NV + c] + bb;

    const bool is_g = (role == 2);

    for (int s = 0; s < SEQ; ++s) {
        // prefetch next step's xz components (L2-resident table)
        const int sn = (s + 1 < SEQ) ? s + 1 : s;
        float m0 = g_M[idx_s[sn] * NV + c];
        float m1 = g_M[idx_s[SEQ + sn] * NV + c];
        float m2 = g_M[idx_s[2 * SEQ + sn] * NV + c];
        float m3 = g_M[idx_s[3 * SEQ + sn] * NV + c];

        // z = xz + h . Wh[:,c]   (4 independent f32x2 chains)
        const ulonglong2* hp = (const ulonglong2*)((s & 1) ? h1 : h0);
        ull a0 = pk(xz, 0.f), a1 = 0ull, a2 = 0ull, a3 = 0ull;
#pragma unroll
        for (int g = 0; g < RGRP4; ++g) {        // 12 groups x 4 = 48 fp32 rows
            ulonglong2 hv = hp[g];               // broadcast LDS.128
            if (g & 1) { FMA2(a2, hv.x, wp[2 * g]); FMA2(a3, hv.y, wp[2 * g + 1]); }
            else       { FMA2(a0, hv.x, wp[2 * g]); FMA2(a1, hv.y, wp[2 * g + 1]); }
        }
#pragma unroll
        for (int g = 0; g < FGRP4; ++g) {        // 20 groups x 4 = 80 fp16 rows
            ulonglong2 hv = hp[RGRP4 + g];       // broadcast LDS.128
            if (g & 1) { FMA2(a2, hv.x, h2f2(fw[2 * g])); FMA2(a3, hv.y, h2f2(fw[2 * g + 1])); }
            else       { FMA2(a0, hv.x, h2f2(fw[2 * g])); FMA2(a1, hv.y, h2f2(fw[2 * g + 1])); }
        }
        float z = red4(a0, a1, a2, a3);

        // activation for own gate
        float act = is_g ? tanh_f(z) : sigmoid_f(z);

        // assemble i,f,g,o in role-0 lane: 3 shuffles
        float xb = __shfl_xor_sync(0xffffffffu, act, 8);   // role0 <- f
        float xg = __shfl_xor_sync(0xffffffffu, act, 16);  // role0 <- g
        float xo = __shfl_xor_sync(0xffffffffu, xg, 8);    // role0 <- o

        float* hw = (s & 1) ? h0 : h1;
        if (role == 0) {
            float cn = fmaf(xb, c_r, act * xg);            // f*c + i*g
            c_r = cn;
            float hn = xo * tanh_f(cn);
            hw[e] = hn;
            out_h[(b * SEQ + s) * UNITS + e] = hn;
            h_last = hn;
        }
        xz = m0 + m1 + m2 + m3 + bb;
        __syncthreads();
    }
    if (role == 0) out_lv[b * UNITS + e] = h_last;
}

// ---------------------------------------------------------------------------
extern "C" void kernel_launch(void* const* d_in, const int* in_sizes, int n_in,
                              void* d_out, int out_size) {
    const int*   move_count   = (const int*)d_in[0];
    // d_in[1] = moves_remaining (unused by reference)
    const int*   last_rule    = (const int*)d_in[2];
    const int*   node_count   = (const int*)d_in[3];
    const int*   problem_type = (const int*)d_in[4];
    const int*   bwd          = (const int*)d_in[5];
    const int*   fwd          = (const int*)d_in[6];
    const int*   lbwd         = (const int*)d_in[7];
    const int*   lfwd         = (const int*)d_in[8];
    const float* Wd           = (const float*)d_in[9];
    const float* b_dense      = (const float*)d_in[10];
    const float* Wx           = (const float*)d_in[11];
    const float* Wh           = (const float*)d_in[12];
    const float* b_lstm       = (const float*)d_in[13];
    float* out = (float*)d_out;

    prep_bb_kernel<<<1, NV>>>(b_dense, Wx, b_lstm);
    prep_M_kernel<<<KROWS / RPB, 512>>>(Wd, Wx);
    ctx_kernel<<<BATCH, 64>>>(last_rule, move_count, node_count, problem_type, out, out_size);

    const int off_lv = BATCH * 35;                 // 4480
    const int off_h  = off_lv + BATCH * UNITS;     // 20864
    lstm_kernel<<<BATCH, NT, SMEM_LSTM>>>(bwd, fwd, lbwd, lfwd, Wh,
                                          out + off_h, out + off_lv);
}